// round 9
// baseline (speedup 1.0000x reference)
#include <cuda_runtime.h>
#include <cuda_bf16.h>
#include <cstdint>

#define NB 64
#define NN 512
#define ND 128

// pre-normalized features, bf16 hi/lo planes
__device__ uint4 g_hi[(NB * NN * ND * 2) / 16];
__device__ uint4 g_lo[(NB * NN * ND * 2) / 16];

__device__ __forceinline__ uint32_t smem_u32(const void* p) {
    uint32_t a;
    asm("{ .reg .u64 t; cvta.to.shared.u64 t, %1; cvt.u32.u64 %0, t; }" : "=r"(a) : "l"(p));
    return a;
}
__device__ __forceinline__ float fsqrt_approx(float x) {
    float r;
    asm("sqrt.approx.f32 %0, %1;" : "=f"(r) : "f"(x));
    return r;
}

#define LDSM_X4(r, addr)                                                                  \
    asm volatile("ldmatrix.sync.aligned.m8n8.x4.shared.b16 {%0,%1,%2,%3}, [%4];"          \
                 : "=r"((r)[0]), "=r"((r)[1]), "=r"((r)[2]), "=r"((r)[3]) : "r"(addr))

#define CP_ASYNC16(sa, gp)                                                                \
    asm volatile("cp.async.cg.shared.global [%0], [%1], 16;" :: "r"(sa), "l"(gp) : "memory")
#define CP_COMMIT() asm volatile("cp.async.commit_group;" ::: "memory")
#define CP_WAIT(n)  asm volatile("cp.async.wait_group %0;" :: "n"(n) : "memory")

__device__ __forceinline__ void mma16816(float* c, uint32_t a0, uint32_t a1, uint32_t a2,
                                         uint32_t a3, uint32_t b0, uint32_t b1) {
    asm volatile("mma.sync.aligned.m16n8k16.row.col.f32.bf16.bf16.f32 "
                 "{%0,%1,%2,%3}, {%4,%5,%6,%7}, {%8,%9}, {%0,%1,%2,%3};"
                 : "+f"(c[0]), "+f"(c[1]), "+f"(c[2]), "+f"(c[3])
                 : "r"(a0), "r"(a1), "r"(a2), "r"(a3), "r"(b0), "r"(b1));
}

// smem: 64x64 jobs, K-chunk 32. Row stride 80 B (r*80 mod 128B cycles all 8
// 16B-banks -> conflict-free ldmatrix). Planes: Ahi, Alo, Bhi, Blo, 64 rows each.
#define SMA32 80
#define PLANE 5120            // 64*80
#define CHUNK 20480           // 4 planes
#define OFF_CI 40960          // 64 float2
#define OFF_CJ 41472
#define SMEM_TOTAL 41984
#define OFF_AVT 0             // 64*68*4 = 17408, reuses buffers after MMA
#define AVT_S 68              // write phase: q*2*68 mod 32-banks = q*8 -> conflict-free

// ---------- prep: normalize rows, split to bf16 hi/lo ----------
__global__ void prep_kernel(const float* __restrict__ fea) {
    int row  = blockIdx.x * 8 + (threadIdx.x >> 5);
    int lane = threadIdx.x & 31;
    float4 v = reinterpret_cast<const float4*>(fea + (size_t)row * ND)[lane];
    float s = v.x * v.x + v.y * v.y + v.z * v.z + v.w * v.w;
    #pragma unroll
    for (int o = 16; o > 0; o >>= 1) s += __shfl_xor_sync(0xffffffffu, s, o);
    float rn = 1.0f / fmaxf(sqrtf(s), 1e-8f);
    float x0 = v.x * rn, x1 = v.y * rn, x2 = v.z * rn, x3 = v.w * rn;
    __nv_bfloat16 h0 = __float2bfloat16(x0), h1 = __float2bfloat16(x1);
    __nv_bfloat16 h2 = __float2bfloat16(x2), h3 = __float2bfloat16(x3);
    __nv_bfloat16 l0 = __float2bfloat16(x0 - __bfloat162float(h0));
    __nv_bfloat16 l1 = __float2bfloat16(x1 - __bfloat162float(h1));
    __nv_bfloat16 l2 = __float2bfloat16(x2 - __bfloat162float(h2));
    __nv_bfloat16 l3 = __float2bfloat16(x3 - __bfloat162float(h3));
    uint2 hv, lv;
    hv.x = (uint32_t)__bfloat16_as_ushort(h0) | ((uint32_t)__bfloat16_as_ushort(h1) << 16);
    hv.y = (uint32_t)__bfloat16_as_ushort(h2) | ((uint32_t)__bfloat16_as_ushort(h3) << 16);
    lv.x = (uint32_t)__bfloat16_as_ushort(l0) | ((uint32_t)__bfloat16_as_ushort(l1) << 16);
    lv.y = (uint32_t)__bfloat16_as_ushort(l2) | ((uint32_t)__bfloat16_as_ushort(l3) << 16);
    reinterpret_cast<uint2*>(g_hi)[(size_t)row * 32 + lane] = hv;
    reinterpret_cast<uint2*>(g_lo)[(size_t)row * 32 + lane] = lv;
}

// issue one K32 chunk: 4 planes x 64 rows x 32 bf16 = 1024 uint4 = 4/thread
__device__ __forceinline__ void issue_chunk(uint32_t bufBase, int tid, int b,
                                            int iBase, int jBase, int kc) {
    #pragma unroll
    for (int it = 0; it < 4; it++) {
        int idx = tid + it * 256;
        int plane = idx >> 8;              // 0 Ahi, 1 Alo, 2 Bhi, 3 Blo
        int e = idx & 255;
        int row = e >> 2;
        int c8 = (e & 3) * 8;
        int grow = ((plane < 2) ? iBase : jBase) + row;
        const uint4* src = (plane & 1) ? g_lo : g_hi;
        const uint4* gp = &src[((size_t)(b * NN + grow) * ND + kc * 32 + c8) >> 3];
        uint32_t sa = bufBase + (uint32_t)(plane * PLANE + row * SMA32 + c8 * 2);
        CP_ASYNC16(sa, gp);
    }
    CP_COMMIT();
}

// ---------- main: 64x64 jobs, 256 threads, 4 CTAs/SM ----------
__global__ __launch_bounds__(256, 4)
void adj_mma_kernel(const float* __restrict__ coord, float* __restrict__ out) {
    extern __shared__ char sm[];
    const uint32_t smb = smem_u32(sm);
    const int tid  = threadIdx.x;
    const int wid  = tid >> 5;
    const int lane = tid & 31;
    const int wy = wid & 1;           // 0..1, m dim (32 rows)
    const int wx = wid >> 1;          // 0..3, n dim (16 cols)

    const int blk = blockIdx.x;
    const int b = blk / 36;
    const int t = blk % 36;
    const unsigned char bi_t[36] = {0,0,0,0,0,0,0,0, 1,1,1,1,1,1,1, 2,2,2,2,2,2,
                                    3,3,3,3,3, 4,4,4,4, 5,5,5, 6,6, 7};
    const unsigned char bj_t[36] = {0,1,2,3,4,5,6,7, 1,2,3,4,5,6,7, 2,3,4,5,6,7,
                                    3,4,5,6,7, 4,5,6,7, 5,6,7, 6,7, 7};
    const int iBase = bi_t[t] * 64;
    const int jBase = bj_t[t] * 64;
    const bool diag = (iBase == jBase);

    // prologue: chunks 0,1 in flight
    issue_chunk(smb,         tid, b, iBase, jBase, 0);
    issue_chunk(smb + CHUNK, tid, b, iBase, jBase, 1);

    // stage coords while loads stream
    {
        float2* ci2 = reinterpret_cast<float2*>(sm + OFF_CI);
        float2* cj2 = reinterpret_cast<float2*>(sm + OFF_CJ);
        if (tid < 64)
            ci2[tid] = reinterpret_cast<const float2*>(coord)[(size_t)b * NN + iBase + tid];
        else if (tid < 128)
            cj2[tid - 64] = reinterpret_cast<const float2*>(coord)[(size_t)b * NN + jBase + (tid - 64)];
    }

    float acc[2][2][4];
    #pragma unroll
    for (int mt = 0; mt < 2; mt++)
        #pragma unroll
        for (int nt = 0; nt < 2; nt++)
            #pragma unroll
            for (int q = 0; q < 4; q++) acc[mt][nt][q] = 0.0f;

    const uint32_t aOff = (uint32_t)((wy * 32 + lane) * SMA32);
    // folded B addressing: lanes 0-15 -> rows @k0-7, lanes 16-31 -> same rows @k8-15
    const uint32_t bOff = (uint32_t)(2 * PLANE + (wx * 16 + (lane & 15)) * SMA32 + (lane >> 4) * 16);

    #pragma unroll
    for (int kc = 0; kc < 4; kc++) {
        if (kc < 3) CP_WAIT(1); else CP_WAIT(0);
        __syncthreads();

        const uint32_t buf = smb + (uint32_t)((kc & 1) * CHUNK);
        const uint32_t aH = buf + aOff;
        const uint32_t aL = aH + PLANE;
        const uint32_t bH = buf + bOff;
        const uint32_t bL = bH + PLANE;

        #pragma unroll
        for (int ks = 0; ks < 2; ks++) {
            const uint32_t co = (uint32_t)(ks * 32);
            uint32_t ah1[4], ah2[4], bh[4];
            LDSM_X4(ah1, aH + co);
            LDSM_X4(ah2, aH + co + 16);
            LDSM_X4(bh, bH + co);      // bh[nt] = n-grp nt k0-7, bh[nt+2] = k8-15
            #pragma unroll
            for (int mt = 0; mt < 2; mt++)
                #pragma unroll
                for (int nt = 0; nt < 2; nt++)
                    mma16816(acc[mt][nt], ah1[mt*2], ah1[mt*2+1], ah2[mt*2], ah2[mt*2+1],
                             bh[nt], bh[nt+2]);
            {
                uint32_t bl[4];
                LDSM_X4(bl, bL + co);
                #pragma unroll
                for (int mt = 0; mt < 2; mt++)
                    #pragma unroll
                    for (int nt = 0; nt < 2; nt++)
                        mma16816(acc[mt][nt], ah1[mt*2], ah1[mt*2+1], ah2[mt*2], ah2[mt*2+1],
                                 bl[nt], bl[nt+2]);
            }
            {
                uint32_t al1[4], al2[4];
                LDSM_X4(al1, aL + co);
                LDSM_X4(al2, aL + co + 16);
                #pragma unroll
                for (int mt = 0; mt < 2; mt++)
                    #pragma unroll
                    for (int nt = 0; nt < 2; nt++)
                        mma16816(acc[mt][nt], al1[mt*2], al1[mt*2+1], al2[mt*2], al2[mt*2+1],
                                 bh[nt], bh[nt+2]);
            }
        }

        __syncthreads();
        if (kc < 2) issue_chunk(buf, tid, b, iBase, jBase, kc + 2);
    }

    // epilogue: direct stores from fragments + transposed staging for mirror
    {
        const float2* ci2 = reinterpret_cast<const float2*>(sm + OFF_CI);
        const float2* cj2 = reinterpret_cast<const float2*>(sm + OFF_CJ);
        float* avt = reinterpret_cast<float*>(sm + OFF_AVT);
        float* outA = out;
        float* outS = out + (size_t)NB * NN * NN;
        const size_t base = (size_t)b * NN * NN;
        const int g = lane >> 2, q = lane & 3;

        #pragma unroll
        for (int mt = 0; mt < 2; mt++) {
            #pragma unroll
            for (int nt = 0; nt < 2; nt++) {
                const float* c = acc[mt][nt];
                const int lj = wx * 16 + nt * 8 + q * 2;       // 0..63
                const float2 cj0 = cj2[lj], cj1 = cj2[lj + 1];
                #pragma unroll
                for (int h = 0; h < 2; h++) {
                    const int li = wy * 32 + mt * 16 + g + h * 8;   // 0..63
                    const float2 ci = ci2[li];
                    float dx0 = ci.x - cj0.x, dy0 = ci.y - cj0.y;
                    float dx1 = ci.x - cj1.x, dy1 = ci.y - cj1.y;
                    float d20 = dx0 * dx0 + dy0 * dy0;
                    float d21 = dx1 * dx1 + dy1 * dy1;
                    bool s0 = diag && (li == lj);
                    bool s1 = diag && (li == lj + 1);
                    float av0 = s0 ? 0.0f : c[h * 2 + 0] * __expf(-fsqrt_approx(d20));
                    float av1 = s1 ? 0.0f : c[h * 2 + 1] * __expf(-fsqrt_approx(d21));
                    float sv0 = (!s0 && d20 < 1.0f) ? 1.0f : 0.0f;
                    float sv1 = (!s1 && d21 < 1.0f) ? 1.0f : 0.0f;
                    size_t ro = base + (size_t)(iBase + li) * NN + jBase + lj;
                    *reinterpret_cast<float2*>(outA + ro) = make_float2(av0, av1);
                    *reinterpret_cast<float2*>(outS + ro) = make_float2(sv0, sv1);
                    if (!diag) {
                        avt[(size_t)lj * AVT_S + li]       = av0;
                        avt[(size_t)(lj + 1) * AVT_S + li] = av1;
                    }
                }
            }
        }
    }

    // mirror pass: 64 rows (j) x 64 cols (i)
    if (!diag) {
        __syncthreads();
        const float* avt = reinterpret_cast<const float*>(sm + OFF_AVT);
        const float2* cj2 = reinterpret_cast<const float2*>(sm + OFF_CJ);
        const float4* ci4 = reinterpret_cast<const float4*>(sm + OFF_CI);
        float* outA = out;
        float* outS = out + (size_t)NB * NN * NN;
        const size_t base = (size_t)b * NN * NN;

        #pragma unroll
        for (int it = 0; it < 8; it++) {
            const int r = wid * 8 + it;     // local j row, 0..63
            float2 av2 = *reinterpret_cast<const float2*>(avt + (size_t)r * AVT_S + lane * 2);
            float2 cj = cj2[r];
            float4 p = ci4[lane];           // coords of cols lane*2, lane*2+1
            float d0x = cj.x - p.x, d0y = cj.y - p.y;
            float d1x = cj.x - p.z, d1y = cj.y - p.w;
            float2 sv2;
            sv2.x = (d0x * d0x + d0y * d0y < 1.0f) ? 1.0f : 0.0f;
            sv2.y = (d1x * d1x + d1y * d1y < 1.0f) ? 1.0f : 0.0f;
            size_t ro = base + (size_t)(jBase + r) * NN + iBase + lane * 2;
            *reinterpret_cast<float2*>(outA + ro) = av2;
            *reinterpret_cast<float2*>(outS + ro) = sv2;
        }
    }
}

extern "C" void kernel_launch(void* const* d_in, const int* in_sizes, int n_in,
                              void* d_out, int out_size) {
    (void)in_sizes; (void)n_in; (void)out_size;
    const float* fea   = (const float*)d_in[0];
    const float* coord = (const float*)d_in[1];
    float* out = (float*)d_out;

    prep_kernel<<<NB * NN / 8, 256>>>(fea);

    cudaFuncSetAttribute(adj_mma_kernel, cudaFuncAttributeMaxDynamicSharedMemorySize, SMEM_TOTAL);
    adj_mma_kernel<<<NB * 36, 256, SMEM_TOTAL>>>(coord, out);
}